// round 10
// baseline (speedup 1.0000x reference)
#include <cuda_runtime.h>
#include <cuda_bf16.h>
#include <cstdint>

// ---------------- Problem constants ----------------
#define NROWS 16384
#define DIN   4096
#define DOUT  4096

// Does this device pass support tcgen05 (arch-specific 'a' target)?
#if defined(__CUDA_ARCH__) && (defined(__CUDA_ARCH_FEAT_SM103_ALL) || defined(__CUDA_ARCH_FEAT_SM100_ALL) || defined(__CUDA_ARCH_FEAT_SM101_ALL))
#define USE_TCGEN05 1
#else
#define USE_TCGEN05 0
#endif

// ---------------- Scratch (static __device__, allocation-free) ----------------
__device__ __nv_bfloat16 g_Aq[(size_t)NROWS * DIN];   // quantized activations, [M,K] row-major
__device__ __nv_bfloat16 g_Bq[(size_t)DOUT * DIN];    // quantized weights transposed, [N,K] row-major
__device__ unsigned g_max[2];                          // absmax bits of inputs / kernel

// ---------------- Common helpers ----------------
__device__ __forceinline__ uint32_t smem_to_u32(const void* p) {
    uint32_t a;
    asm("{ .reg .u64 t; cvta.to.shared.u64 t, %1; cvt.u32.u64 %0, t; }" : "=r"(a) : "l"(p));
    return a;
}

// ---- base-PTX (sm_80+) primitives for the fallback path ----
#define CP_ASYNC16(dst, src) \
    asm volatile("cp.async.cg.shared.global [%0], [%1], 16;" :: "r"(dst), "l"(src) : "memory")
#define CP_COMMIT() asm volatile("cp.async.commit_group;" ::: "memory")
#define CP_WAIT(n)  asm volatile("cp.async.wait_group %0;" :: "n"(n) : "memory")

__device__ __forceinline__ void ldsm_x4(uint32_t* r, uint32_t addr) {
    asm volatile("ldmatrix.sync.aligned.m8n8.x4.shared.b16 {%0,%1,%2,%3}, [%4];"
                 : "=r"(r[0]), "=r"(r[1]), "=r"(r[2]), "=r"(r[3]) : "r"(addr));
}
__device__ __forceinline__ void mma16816(float* c, const uint32_t* a, const uint32_t* b) {
    asm volatile(
        "mma.sync.aligned.m16n8k16.row.col.f32.bf16.bf16.f32 "
        "{%0,%1,%2,%3}, {%4,%5,%6,%7}, {%8,%9}, {%0,%1,%2,%3};"
        : "+f"(c[0]), "+f"(c[1]), "+f"(c[2]), "+f"(c[3])
        : "r"(a[0]), "r"(a[1]), "r"(a[2]), "r"(a[3]), "r"(b[0]), "r"(b[1]));
}

// ---- tcgen05 primitives (only compiled in 'a'-target passes) ----
#if USE_TCGEN05
#define TCGEN05_ALLOC(smem_result_addr, nCols) \
    asm volatile("tcgen05.alloc.cta_group::1.sync.aligned.shared::cta.b32 [%0], %1;" \
                 :: "r"((uint32_t)(smem_result_addr)), "r"((uint32_t)(nCols)) : "memory")
#define TCGEN05_DEALLOC(tmem_addr, nCols) \
    asm volatile("tcgen05.dealloc.cta_group::1.sync.aligned.b32 %0, %1;" \
                 :: "r"(tmem_addr), "r"((uint32_t)(nCols)))
#define TCGEN05_RELINQUISH() \
    asm volatile("tcgen05.relinquish_alloc_permit.cta_group::1.sync.aligned;")
#define TCGEN05_COMMIT(mbar_smem_addr) \
    asm volatile("tcgen05.commit.cta_group::1.mbarrier::arrive::one.shared::cluster.b64 [%0];" \
                 :: "r"((uint32_t)(mbar_smem_addr)) : "memory")
#define TCGEN05_WAIT_LD() asm volatile("tcgen05.wait::ld.sync.aligned;" ::: "memory")
#define TCGEN05_FENCE_AFTER() asm volatile("tcgen05.fence::after_thread_sync;" ::: "memory")
#define TCGEN05_FENCE_BEFORE() asm volatile("tcgen05.fence::before_thread_sync;" ::: "memory")
#define MBARRIER_INIT(mbar, count) \
    asm volatile("mbarrier.init.shared.b64 [%0], %1;" :: "r"((uint32_t)(mbar)), "r"((uint32_t)(count)) : "memory")

#define MBARRIER_WAIT_PARITY(mbar_smem_addr, phase_parity) do { \
    uint32_t _mbar = (uint32_t)(mbar_smem_addr); \
    uint32_t _parity = (uint32_t)(phase_parity); \
    uint32_t _done; \
    asm volatile( \
        "{\n\t.reg .pred p;\n\t" \
        "mbarrier.try_wait.parity.acquire.cta.shared::cta.b64 p, [%1], %2;\n\t" \
        "selp.b32 %0, 1, 0, p;\n\t}" \
        : "=r"(_done) : "r"(_mbar), "r"(_parity) : "memory"); \
    if (!_done) { \
        asm volatile( \
            "{\n\t.reg .pred P1;\n\t" \
            "WAIT_LOOP_%=:\n\t" \
            "mbarrier.try_wait.parity.acquire.cta.shared::cta.b64 P1, [%0], %1, 0x989680;\n\t" \
            "@P1 bra.uni WAIT_DONE_%=;\n\t" \
            "bra.uni WAIT_LOOP_%=;\n\t" \
            "WAIT_DONE_%=:\n\t}" \
            :: "r"(_mbar), "r"(_parity) : "memory"); \
    } \
} while(0)

#define TCGEN05_LD_32X32B_X32(r, tmem_addr) \
    asm volatile( \
        "tcgen05.ld.sync.aligned.32x32b.x32.b32 " \
        "{%0, %1, %2, %3, %4, %5, %6, %7, " \
        " %8, %9, %10, %11, %12, %13, %14, %15, " \
        " %16, %17, %18, %19, %20, %21, %22, %23, " \
        " %24, %25, %26, %27, %28, %29, %30, %31}, [%32];" \
        : "=r"((r)[0]),  "=r"((r)[1]),  "=r"((r)[2]),  "=r"((r)[3]), \
          "=r"((r)[4]),  "=r"((r)[5]),  "=r"((r)[6]),  "=r"((r)[7]), \
          "=r"((r)[8]),  "=r"((r)[9]),  "=r"((r)[10]), "=r"((r)[11]), \
          "=r"((r)[12]), "=r"((r)[13]), "=r"((r)[14]), "=r"((r)[15]), \
          "=r"((r)[16]), "=r"((r)[17]), "=r"((r)[18]), "=r"((r)[19]), \
          "=r"((r)[20]), "=r"((r)[21]), "=r"((r)[22]), "=r"((r)[23]), \
          "=r"((r)[24]), "=r"((r)[25]), "=r"((r)[26]), "=r"((r)[27]), \
          "=r"((r)[28]), "=r"((r)[29]), "=r"((r)[30]), "=r"((r)[31]) \
        : "r"(tmem_addr))

static constexpr uint64_t SMEM_DESC_BASE_SW128 =
    (uint64_t(2) << 61) | (uint64_t(1) << 46) | (uint64_t(64) << 32) | (uint64_t(1) << 16);
#define MAKE_SMEM_DESC(base_addr) (SMEM_DESC_BASE_SW128 | ((uint64_t)((base_addr) >> 4) & 0x3FFF))

__device__ __forceinline__ void mma_f16_ss_cg1(uint32_t d_tmem, uint64_t a_desc, uint64_t b_desc,
                                               uint32_t idesc, uint32_t en) {
    asm volatile(
        "{\n\t.reg .pred p;\n\t"
        "setp.ne.u32 p, %5, 0;\n\t"
        "tcgen05.mma.cta_group::1.kind::f16 [%0], %1, %2, %3, {%4, %4, %4, %4}, p;\n\t}"
        :: "r"(d_tmem), "l"(a_desc), "l"(b_desc), "r"(idesc), "r"(0u), "r"(en)
        : "memory");
}
#endif // USE_TCGEN05

// ---------------- Kernel 0: zero the absmax accumulators ----------------
__global__ void init_kernel() {
    g_max[0] = 0u;
    g_max[1] = 0u;
}

// ---------------- Kernel 1: absmax reduction (float4 grid-stride) ----------------
__global__ void absmax_kernel(const float4* __restrict__ x, int n4, int which) {
    float m = 0.f;
    for (int i = blockIdx.x * blockDim.x + threadIdx.x; i < n4; i += gridDim.x * blockDim.x) {
        float4 v = x[i];
        m = fmaxf(m, fmaxf(fmaxf(fabsf(v.x), fabsf(v.y)), fmaxf(fabsf(v.z), fabsf(v.w))));
    }
    #pragma unroll
    for (int o = 16; o; o >>= 1) m = fmaxf(m, __shfl_xor_sync(0xFFFFFFFFu, m, o));
    __shared__ float sm[8];
    int wid = threadIdx.x >> 5, lid = threadIdx.x & 31;
    if (lid == 0) sm[wid] = m;
    __syncthreads();
    if (threadIdx.x < 32) {
        m = (threadIdx.x < (blockDim.x >> 5)) ? sm[threadIdx.x] : 0.f;
        #pragma unroll
        for (int o = 4; o; o >>= 1) m = fmaxf(m, __shfl_xor_sync(0xFFFFFFFFu, m, o));
        if (threadIdx.x == 0) atomicMax(&g_max[which], __float_as_uint(m));
    }
}

// ---------------- Kernel 2: quantize activations -> integer-valued bf16 ----------------
__global__ void quantA_kernel(const float4* __restrict__ x, int n4) {
    const float inv = 127.f / (__uint_as_float(g_max[0]) + 1e-8f);
    uint2* out = (uint2*)g_Aq;
    for (int i = blockIdx.x * blockDim.x + threadIdx.x; i < n4; i += gridDim.x * blockDim.x) {
        float4 v = x[i];
        __nv_bfloat162 lo = __floats2bfloat162_rn(rintf(v.x * inv), rintf(v.y * inv));
        __nv_bfloat162 hi = __floats2bfloat162_rn(rintf(v.z * inv), rintf(v.w * inv));
        uint2 o;
        o.x = *reinterpret_cast<uint32_t*>(&lo);
        o.y = *reinterpret_cast<uint32_t*>(&hi);
        out[i] = o;
    }
}

// ---------------- Kernel 3: transpose + quantize weights -> [N,K] bf16 ----------------
__global__ void quantB_kernel(const float* __restrict__ w) {
    __shared__ float tile[32][33];
    int n0 = blockIdx.x * 32;
    int k0 = blockIdx.y * 32;
    int tx = threadIdx.x, ty = threadIdx.y;   // block (32, 8)
    #pragma unroll
    for (int j = 0; j < 32; j += 8)
        tile[ty + j][tx] = w[(size_t)(k0 + ty + j) * DOUT + n0 + tx];
    __syncthreads();
    const float inv = 127.f / (__uint_as_float(g_max[1]) + 1e-8f);
    #pragma unroll
    for (int j = 0; j < 32; j += 8) {
        float q = rintf(tile[tx][ty + j] * inv);  // w[k0+tx][n0+ty+j]
        g_Bq[(size_t)(n0 + ty + j) * DIN + (k0 + tx)] = __float2bfloat16(q);
    }
}

// ---------------- Kernel 4: GEMM, 128x256 output tile per CTA ----------------
// Both code paths use grid (DOUT/256, NROWS/128), 256 threads.
static constexpr int GTHREADS = 256;

// tcgen05 path layout (superset smem budget; fallback needs 61440B)
static constexpr int TG_A_BYTES = 128 * 128;            // 16KB per stage
static constexpr int TG_B_BYTES = 256 * 128;            // 32KB per stage
static constexpr int OFF_A0 = 1024;
static constexpr int OFF_A1 = OFF_A0 + TG_A_BYTES;
static constexpr int OFF_B0 = OFF_A1 + TG_A_BYTES;
static constexpr int OFF_B1 = OFF_B0 + TG_B_BYTES;
static constexpr int SMEM_BYTES = OFF_B1 + TG_B_BYTES + 1024;  // ~99KB

#if USE_TCGEN05
// idesc: F32 accum, BF16 x BF16, N=128, M=128 (cg1) — two N=128 MMAs cover BN=256
static constexpr uint32_t IDESC_N128 =
    (1u << 4) | (1u << 7) | (1u << 10) | ((128u / 8) << 17) | ((128u / 16) << 24);
#endif

__global__ void __launch_bounds__(GTHREADS)
gemm_kernel(const float* __restrict__ bias, float* __restrict__ out) {
#if USE_TCGEN05
    // ================= tcgen05 path (sm_103a cubin) =================
    extern __shared__ char smem_raw[];
    uint32_t sb_raw = smem_to_u32(smem_raw);
    uint32_t sb = (sb_raw + 1023u) & ~1023u;            // 1024-align for SW128 descriptors
    char* sm = smem_raw + (sb - sb_raw);

    int tid = threadIdx.x, wid = tid >> 5, lid = tid & 31;
    int m0 = blockIdx.y * 128;
    int n0 = blockIdx.x * 256;

    if (wid == 0) { TCGEN05_ALLOC(sb + 0, 256); }
    if (tid == 0) { MBARRIER_INIT(sb + 16, 1); MBARRIER_INIT(sb + 24, 1); }
    __syncthreads();
    uint32_t tmem;
    asm volatile("ld.shared.b32 %0, [%1];" : "=r"(tmem) : "r"(sb + 0));

    const __nv_bfloat16* Ag = g_Aq + (size_t)m0 * DIN;
    const __nv_bfloat16* Bg = g_Bq + (size_t)n0 * DIN;

    int ph0 = 0, ph1 = 0;
    const int ITERS = DIN / 64;  // 64 K-chunks of 64

    for (int it = 0; it < ITERS; ++it) {
        int buf = it & 1;
        int offA = buf ? OFF_A1 : OFF_A0;
        int offB = buf ? OFF_B1 : OFF_B0;

        if (it >= 2) {
            if (buf == 0) { MBARRIER_WAIT_PARITY(sb + 16, ph0); ph0 ^= 1; }
            else          { MBARRIER_WAIT_PARITY(sb + 24, ph1); ph1 ^= 1; }
        }

        #pragma unroll
        for (int j = 0; j < 4; j++) {          // A: 128 rows x 64 bf16
            int qidx = tid + j * GTHREADS;
            int r = qidx >> 3, q = qidx & 7;
            uint4 v = *((const uint4*)(Ag + (size_t)r * DIN + it * 64) + q);
            uint32_t off = (uint32_t)(r * 128 + q * 16);
            uint32_t sw = off ^ ((off >> 3) & 0x70);
            *(uint4*)(sm + offA + sw) = v;
        }
        #pragma unroll
        for (int j = 0; j < 8; j++) {          // B: 256 rows x 64 bf16
            int qidx = tid + j * GTHREADS;
            int r = qidx >> 3, q = qidx & 7;
            uint4 v = *((const uint4*)(Bg + (size_t)r * DIN + it * 64) + q);
            uint32_t off = (uint32_t)(r * 128 + q * 16);
            uint32_t sw = off ^ ((off >> 3) & 0x70);
            *(uint4*)(sm + offB + sw) = v;
        }
        __syncthreads();

        if (tid == 0) {
            asm volatile("fence.proxy.async.shared::cta;" ::: "memory");
            uint64_t adesc  = MAKE_SMEM_DESC(sb + offA);
            uint64_t bdesc0 = MAKE_SMEM_DESC(sb + offB);
            uint64_t bdesc1 = MAKE_SMEM_DESC(sb + offB + 16384);  // B rows 128..255
            #pragma unroll
            for (int ks = 0; ks < 4; ++ks) {
                uint32_t en = (it > 0 || ks > 0) ? 1u : 0u;
                mma_f16_ss_cg1(tmem,       adesc + ks * 2, bdesc0 + ks * 2, IDESC_N128, en);
                mma_f16_ss_cg1(tmem + 128, adesc + ks * 2, bdesc1 + ks * 2, IDESC_N128, en);
            }
            TCGEN05_COMMIT(sb + (buf ? 24 : 16));
        }
    }

    MBARRIER_WAIT_PARITY(sb + 16, ph0);
    MBARRIER_WAIT_PARITY(sb + 24, ph1);
    TCGEN05_FENCE_AFTER();

    float sA = __uint_as_float(g_max[0]) + 1e-8f;
    float sB = __uint_as_float(g_max[1]) + 1e-8f;
    float fscale = sA * sB * (1.f / 16129.f);

    if (wid < 4) {
        int m = m0 + wid * 32 + lid;
        float* orow = out + (size_t)m * DOUT + n0;
        #pragma unroll
        for (int cc = 0; cc < 256; cc += 32) {
            uint32_t r[32];
            TCGEN05_LD_32X32B_X32(r, tmem + cc);
            TCGEN05_WAIT_LD();
            #pragma unroll
            for (int c = 0; c < 32; c += 4) {
                float4 b = *(const float4*)(bias + n0 + cc + c);
                float4 v;
                v.x = __uint_as_float(r[c + 0]) * fscale + b.x;
                v.y = __uint_as_float(r[c + 1]) * fscale + b.y;
                v.z = __uint_as_float(r[c + 2]) * fscale + b.z;
                v.w = __uint_as_float(r[c + 3]) * fscale + b.w;
                *(float4*)(orow + cc + c) = v;
            }
        }
        TCGEN05_FENCE_BEFORE();
    }

    __syncthreads();
    if (wid == 0) {
        TCGEN05_RELINQUISH();
        TCGEN05_DEALLOC(tmem, 256);
    }

#else
    // ================= base-PTX fallback (plain sm_103 cubin) =================
    // 128x256 CTA tile, 8 warps of 64x64, mma.sync m16n8k16 bf16,
    // cp.async double-buffered BK=32, padded-80B smem rows.
    extern __shared__ char smem_raw[];
    const uint32_t sb = smem_to_u32(smem_raw);
    const int tid = threadIdx.x, lid = tid & 31, wid = tid >> 5;
    const int m0 = blockIdx.y * 128, n0 = blockIdx.x * 256;
    const int wm0 = (wid & 1) * 64, wn0 = (wid >> 1) * 64;

    // smem: A buffers 128x32 (rows padded to 80B) = 10240B each; B 256x32 = 20480B each
    const uint32_t A0 = sb, A1 = sb + 10240, B0 = sb + 20480, B1 = sb + 40960;

    const __nv_bfloat16* Ag = g_Aq + (size_t)m0 * DIN;
    const __nv_bfloat16* Bg = g_Bq + (size_t)n0 * DIN;

    auto load_tiles = [&](int kc, uint32_t a_s, uint32_t b_s) {
        const int kb = kc * 32;
        #pragma unroll
        for (int j = 0; j < 2; j++) {              // A: 512 x 16B
            int idx = tid + j * GTHREADS;
            int r = idx >> 2, c = idx & 3;
            CP_ASYNC16(a_s + r * 80 + c * 16, Ag + (size_t)r * DIN + kb + c * 8);
        }
        #pragma unroll
        for (int j = 0; j < 4; j++) {              // B: 1024 x 16B
            int idx = tid + j * GTHREADS;
            int r = idx >> 2, c = idx & 3;
            CP_ASYNC16(b_s + r * 80 + c * 16, Bg + (size_t)r * DIN + kb + c * 8);
        }
    };

    float acc[4][8][4] = {};
    const uint32_t g = lid >> 3, r8 = lid & 7;
    const int ITERS = DIN / 32;  // 128

    load_tiles(0, A0, B0);
    CP_COMMIT();

    for (int kc = 0; kc < ITERS; ++kc) {
        const uint32_t a_s = (kc & 1) ? A1 : A0;
        const uint32_t b_s = (kc & 1) ? B1 : B0;
        if (kc + 1 < ITERS) {
            load_tiles(kc + 1, (kc & 1) ? A0 : A1, (kc & 1) ? B0 : B1);
            CP_COMMIT();
            CP_WAIT(1);
        } else {
            CP_WAIT(0);
        }
        __syncthreads();

        #pragma unroll
        for (int ks = 0; ks < 2; ++ks) {
            uint32_t a[4][4], b[8][2];
            #pragma unroll
            for (int mi = 0; mi < 4; ++mi) {
                uint32_t row = wm0 + mi * 16 + ((g & 1u) << 3) + r8;
                uint32_t col = ks * 16 + ((g >> 1) << 3);
                ldsm_x4(a[mi], a_s + row * 80 + col * 2);
            }
            #pragma unroll
            for (int p = 0; p < 4; ++p) {
                uint32_t row = wn0 + p * 16 + ((g >> 1) << 3) + r8;
                uint32_t col = ks * 16 + ((g & 1u) << 3);
                uint32_t t[4];
                ldsm_x4(t, b_s + row * 80 + col * 2);
                b[p * 2][0] = t[0]; b[p * 2][1] = t[1];
                b[p * 2 + 1][0] = t[2]; b[p * 2 + 1][1] = t[3];
            }
            #pragma unroll
            for (int mi = 0; mi < 4; ++mi)
                #pragma unroll
                for (int ni = 0; ni < 8; ++ni)
                    mma16816(acc[mi][ni], a[mi], b[ni]);
        }
        __syncthreads();
    }

    // Epilogue
    float sA = __uint_as_float(g_max[0]) + 1e-8f;
    float sB = __uint_as_float(g_max[1]) + 1e-8f;
    float fs = sA * sB * (1.f / 16129.f);

    #pragma unroll
    for (int mi = 0; mi < 4; ++mi) {
        int row = m0 + wm0 + mi * 16 + (lid >> 2);
        #pragma unroll
        for (int ni = 0; ni < 8; ++ni) {
            int col = n0 + wn0 + ni * 8 + ((lid & 3) << 1);
            float b0 = bias[col], b1 = bias[col + 1];
            float2 v0, v1;
            v0.x = acc[mi][ni][0] * fs + b0;
            v0.y = acc[mi][ni][1] * fs + b1;
            v1.x = acc[mi][ni][2] * fs + b0;
            v1.y = acc[mi][ni][3] * fs + b1;
            *(float2*)(out + (size_t)row * DOUT + col) = v0;
            *(float2*)(out + (size_t)(row + 8) * DOUT + col) = v1;
        }
    }
#endif
}

// ---------------- Launch ----------------
extern "C" void kernel_launch(void* const* d_in, const int* in_sizes, int n_in,
                              void* d_out, int out_size) {
    const float* inp  = (const float*)d_in[0];   // [16384, 4096]
    const float* ker  = (const float*)d_in[1];   // [4096, 4096]
    const float* bias = (const float*)d_in[2];   // [4096]
    float* out = (float*)d_out;

    cudaFuncSetAttribute(gemm_kernel, cudaFuncAttributeMaxDynamicSharedMemorySize, SMEM_BYTES);

    init_kernel<<<1, 1>>>();

    absmax_kernel<<<1024, 256>>>((const float4*)inp, (NROWS * DIN) / 4, 0);
    absmax_kernel<<<512, 256>>>((const float4*)ker, (DIN * DOUT) / 4, 1);

    quantA_kernel<<<2048, 256>>>((const float4*)inp, (NROWS * DIN) / 4);

    dim3 bgrid(DOUT / 32, DIN / 32);
    quantB_kernel<<<bgrid, dim3(32, 8)>>>(ker);

    dim3 ggrid(DOUT / 256, NROWS / 128);   // (16, 128); x-fastest -> A-tile reuse in L2
    gemm_kernel<<<ggrid, GTHREADS, SMEM_BYTES>>>(bias, out);
}